// round 4
// baseline (speedup 1.0000x reference)
#include <cuda_runtime.h>
#include <cuda_bf16.h>
#include <stdint.h>
#include <math.h>

// Problem constants
#define Nn 8
#define Tt 256
#define Bb 4
#define Dd 512
#define Vv 32000
#define Mm (Nn*Tt*Bb)          // 8192 rows

// GEMM tiling (int8)
#define BM 128
#define BN 128
#define BKB 64                 // K-bytes per stage (64 int8)
#define NUM_K (Dd/BKB)         // 8
#define NTILES (Vv/BN)         // 250
#define SSTRIDE 80             // 64B data + 16B pad per row (conflict-free)

// ---------------------------------------------------------------------------
// Device scratch
// ---------------------------------------------------------------------------
__device__ __align__(16) int8_t g_Aq[Mm*Dd];     // 4 MB
__device__ __align__(16) int8_t g_Wq[Vv*Dd];     // 16 MB
__device__ float    g_ascale[Mm];
__device__ uint32_t g_wamax_bits;                // max|W| as float bits
__device__ float g_c1v[Mm*NTILES];
__device__ int   g_c1i[Mm*NTILES];
__device__ float g_c2v[Mm*NTILES];
__device__ int   g_c2i[Mm*NTILES];
__device__ int   g_maxidx[Mm];
__device__ float g_scores[Mm];

// ---------------------------------------------------------------------------
__device__ __forceinline__ uint32_t smem_u32(const void* p) {
    uint32_t a;
    asm("{ .reg .u64 t; cvta.to.shared.u64 t, %1; cvt.u32.u64 %0, t; }" : "=r"(a) : "l"(p));
    return a;
}
__device__ __forceinline__ void ldsm_x4(uint32_t& a0, uint32_t& a1, uint32_t& a2,
                                        uint32_t& a3, uint32_t addr) {
    asm volatile("ldmatrix.sync.aligned.m8n8.x4.shared.b16 {%0,%1,%2,%3}, [%4];"
                 : "=r"(a0), "=r"(a1), "=r"(a2), "=r"(a3) : "r"(addr));
}
__device__ __forceinline__ void ldsm_x2(uint32_t& b0, uint32_t& b1, uint32_t addr) {
    asm volatile("ldmatrix.sync.aligned.m8n8.x2.shared.b16 {%0,%1}, [%2];"
                 : "=r"(b0), "=r"(b1) : "r"(addr));
}
__device__ __forceinline__ void mma_s8(int* c, uint32_t a0, uint32_t a1,
                                       uint32_t a2, uint32_t a3,
                                       uint32_t b0, uint32_t b1) {
    asm volatile("mma.sync.aligned.m16n8k32.row.col.s32.s8.s8.s32 "
                 "{%0,%1,%2,%3}, {%4,%5,%6,%7}, {%8,%9}, {%0,%1,%2,%3};"
                 : "+r"(c[0]), "+r"(c[1]), "+r"(c[2]), "+r"(c[3])
                 : "r"(a0), "r"(a1), "r"(a2), "r"(a3), "r"(b0), "r"(b1));
}

__device__ __forceinline__ void top2i_insert(int& v1, int& i1, int& v2, int& i2,
                                             int v, int idx) {
    if (v > v1) { v2 = v1; i2 = i1; v1 = v; i1 = idx; }
    else if (v > v2) { v2 = v; i2 = idx; }
}
__device__ __forceinline__ void top2i_merge(int& v1, int& i1, int& v2, int& i2,
                                            int ov1, int oi1, int ov2, int oi2) {
    if (ov1 > v1) {
        if (v1 > ov2) { v2 = v1; i2 = i1; } else { v2 = ov2; i2 = oi2; }
        v1 = ov1; i1 = oi1;
    } else {
        if (ov1 > v2) { v2 = ov1; i2 = oi1; }
    }
}
__device__ __forceinline__ void top2f_merge(float& v1, int& i1, float& v2, int& i2,
                                            float ov1, int oi1, float ov2, int oi2) {
    if (ov1 > v1) {
        if (v1 > ov2) { v2 = v1; i2 = i1; } else { v2 = ov2; i2 = oi2; }
        v1 = ov1; i1 = oi1;
    } else {
        if (ov1 > v2) { v2 = ov1; i2 = oi1; }
    }
}
__device__ __forceinline__ int8_t q8(float v, float inv) {
    int q = __float2int_rn(v * inv);
    q = max(-127, min(127, q));
    return (int8_t)q;
}

// ---------------------------------------------------------------------------
// Kernel 0a: per-row quantization of A (argmax invariant to per-row scale)
// One warp per row; lane handles elems [lane*16, lane*16+16).
// ---------------------------------------------------------------------------
__global__ void quantA_kernel(const float* __restrict__ A)
{
    const int row = blockIdx.x * 8 + (threadIdx.x >> 5);
    const int lane = threadIdx.x & 31;
    const float* src = A + (size_t)row * Dd + lane * 16;

    float4 f[4];
    float amax = 0.f;
#pragma unroll
    for (int j = 0; j < 4; ++j) {
        f[j] = *(const float4*)(src + j * 4);
        amax = fmaxf(amax, fmaxf(fmaxf(fabsf(f[j].x), fabsf(f[j].y)),
                                 fmaxf(fabsf(f[j].z), fabsf(f[j].w))));
    }
#pragma unroll
    for (int off = 16; off > 0; off >>= 1)
        amax = fmaxf(amax, __shfl_xor_sync(0xffffffffu, amax, off));

    const float inv = (amax > 0.f) ? 127.f / amax : 0.f;
    uint32_t w[4];
#pragma unroll
    for (int j = 0; j < 4; ++j) {
        uint32_t b0 = (uint8_t)q8(f[j].x, inv), b1 = (uint8_t)q8(f[j].y, inv);
        uint32_t b2 = (uint8_t)q8(f[j].z, inv), b3 = (uint8_t)q8(f[j].w, inv);
        w[j] = b0 | (b1 << 8) | (b2 << 16) | (b3 << 24);
    }
    *(uint4*)(g_Aq + (size_t)row * Dd + lane * 16) = make_uint4(w[0], w[1], w[2], w[3]);
    if (lane == 0) g_ascale[row] = amax * (1.f / 127.f);
}

// ---------------------------------------------------------------------------
// Kernel 0b: global max|W| (positive float bits are order-isomorphic to uint)
// ---------------------------------------------------------------------------
__global__ void wmax_kernel(const float* __restrict__ W)
{
    __shared__ float s_mx[256];
    float mx = 0.f;
    const int stride = gridDim.x * blockDim.x;
    for (int i = blockIdx.x * blockDim.x + threadIdx.x; i < Vv * Dd / 4; i += stride) {
        float4 v = ((const float4*)W)[i];
        mx = fmaxf(mx, fmaxf(fmaxf(fabsf(v.x), fabsf(v.y)),
                             fmaxf(fabsf(v.z), fabsf(v.w))));
    }
    s_mx[threadIdx.x] = mx;
    __syncthreads();
    for (int s = 128; s > 0; s >>= 1) {
        if (threadIdx.x < s) s_mx[threadIdx.x] = fmaxf(s_mx[threadIdx.x], s_mx[threadIdx.x + s]);
        __syncthreads();
    }
    if (threadIdx.x == 0)
        atomicMax(&g_wamax_bits, __float_as_uint(s_mx[0]));
}

// ---------------------------------------------------------------------------
// Kernel 0c: quantize W with the global scale
// ---------------------------------------------------------------------------
__global__ void quantW_kernel(const float* __restrict__ W)
{
    const float amax = __uint_as_float(g_wamax_bits);
    const float inv = (amax > 0.f) ? 127.f / amax : 0.f;
    int t = blockIdx.x * blockDim.x + threadIdx.x;     // one uint4 out per thread
    const float* src = W + (size_t)t * 16;
    uint32_t w[4];
#pragma unroll
    for (int j = 0; j < 4; ++j) {
        float4 f = *(const float4*)(src + j * 4);
        uint32_t b0 = (uint8_t)q8(f.x, inv), b1 = (uint8_t)q8(f.y, inv);
        uint32_t b2 = (uint8_t)q8(f.z, inv), b3 = (uint8_t)q8(f.w, inv);
        w[j] = b0 | (b1 << 8) | (b2 << 16) | (b3 << 24);
    }
    *(uint4*)(g_Wq + (size_t)t * 16) = make_uint4(w[0], w[1], w[2], w[3]);
}

// ---------------------------------------------------------------------------
// Kernel 1: int8 IMMA GEMM + exact-int top-2 per (row, vtile) epilogue.
// Grid (64, 250), 256 threads = 8 warps (2 M x 4 N), warp 64x32.
// ---------------------------------------------------------------------------
__global__ void __launch_bounds__(256, 2)
argmax_gemm_kernel()
{
    __shared__ __align__(16) int8_t sA[2][BM * SSTRIDE];
    __shared__ __align__(16) int8_t sB[2][BN * SSTRIDE];

    const int tid = threadIdx.x;
    const int lane = tid & 31, wid = tid >> 5;
    const int wm = wid >> 2, wn = wid & 3;
    const int m0 = blockIdx.x * BM;
    const int v0 = blockIdx.y * BN;

    // Global->smem mapping: 512 uint4 per tile; thread handles rows lr, lr+64
    const int lr = tid >> 2;
    const int lc = (tid & 3) * 16;               // byte col 0,16,32,48
    const int8_t* gA = g_Aq + (size_t)(m0 + lr) * Dd + lc;
    const int8_t* gW = g_Wq + (size_t)(v0 + lr) * Dd + lc;
    const int smoff0 = lr * SSTRIDE + lc;
    const int smoff1 = (lr + 64) * SSTRIDE + lc;

    // ldmatrix per-thread addressing (bytes)
    const int aRow = lane & 15;
    const int aKof = (lane >> 4) * 16;
    const int l2 = lane & 15;
    const int bRow = l2 & 7;
    const int bKof = ((l2 >> 3) & 1) * 16;

    uint32_t sa_base[2], sb_base[2];
    sa_base[0] = smem_u32(sA[0]); sa_base[1] = smem_u32(sA[1]);
    sb_base[0] = smem_u32(sB[0]); sb_base[1] = smem_u32(sB[1]);

    int acc[4][4][4];
#pragma unroll
    for (int a = 0; a < 4; ++a)
#pragma unroll
        for (int b = 0; b < 4; ++b)
#pragma unroll
            for (int c = 0; c < 4; ++c) acc[a][b][c] = 0;

    uint4 ra0, ra1, rb0, rb1;

    ra0 = *(const uint4*)(gA);
    ra1 = *(const uint4*)(gA + (size_t)64 * Dd);
    rb0 = *(const uint4*)(gW);
    rb1 = *(const uint4*)(gW + (size_t)64 * Dd);
    *(uint4*)(sA[0] + smoff0) = ra0; *(uint4*)(sA[0] + smoff1) = ra1;
    *(uint4*)(sB[0] + smoff0) = rb0; *(uint4*)(sB[0] + smoff1) = rb1;
    __syncthreads();

    for (int kt = 0; kt < NUM_K; ++kt) {
        const int buf = kt & 1;
        if (kt + 1 < NUM_K) {
            int g = (kt + 1) * BKB;
            ra0 = *(const uint4*)(gA + g);
            ra1 = *(const uint4*)(gA + g + (size_t)64 * Dd);
            rb0 = *(const uint4*)(gW + g);
            rb1 = *(const uint4*)(gW + g + (size_t)64 * Dd);
        }

#pragma unroll
        for (int s = 0; s < 2; ++s) {            // two k32 steps per 64B stage
            uint32_t bf[4][2];
#pragma unroll
            for (int nf = 0; nf < 4; ++nf) {
                uint32_t addr = sb_base[buf] +
                    (uint32_t)((wn * 32 + nf * 8 + bRow) * SSTRIDE + s * 32 + bKof);
                ldsm_x2(bf[nf][0], bf[nf][1], addr);
            }
#pragma unroll
            for (int mf = 0; mf < 4; ++mf) {
                uint32_t a0, a1, a2, a3;
                uint32_t addr = sa_base[buf] +
                    (uint32_t)((wm * 64 + mf * 16 + aRow) * SSTRIDE + s * 32 + aKof);
                ldsm_x4(a0, a1, a2, a3, addr);
#pragma unroll
                for (int nf = 0; nf < 4; ++nf)
                    mma_s8(acc[mf][nf], a0, a1, a2, a3, bf[nf][0], bf[nf][1]);
            }
        }

        if (kt + 1 < NUM_K) {
            const int nb = buf ^ 1;
            *(uint4*)(sA[nb] + smoff0) = ra0; *(uint4*)(sA[nb] + smoff1) = ra1;
            *(uint4*)(sB[nb] + smoff0) = rb0; *(uint4*)(sB[nb] + smoff1) = rb1;
        }
        __syncthreads();
    }

    // Epilogue: exact-int top-2 per row over this CTA's 128 V-columns
    int4* s_red = (int4*)sA;            // [128][4 N-warps]
    const int colBase = v0 + wn * 32 + (lane & 3) * 2;

#pragma unroll
    for (int mf = 0; mf < 4; ++mf) {
#pragma unroll
        for (int half = 0; half < 2; ++half) {
            int v1 = INT_MIN, v2 = INT_MIN, i1 = 0, i2 = 0;
#pragma unroll
            for (int nf = 0; nf < 4; ++nf) {
#pragma unroll
                for (int c = 0; c < 2; ++c)
                    top2i_insert(v1, i1, v2, i2, acc[mf][nf][half * 2 + c],
                                 colBase + nf * 8 + c);
            }
#pragma unroll
            for (int off = 2; off >= 1; off >>= 1) {
                int ov1 = __shfl_down_sync(0xffffffffu, v1, off, 4);
                int oi1 = __shfl_down_sync(0xffffffffu, i1, off, 4);
                int ov2 = __shfl_down_sync(0xffffffffu, v2, off, 4);
                int oi2 = __shfl_down_sync(0xffffffffu, i2, off, 4);
                top2i_merge(v1, i1, v2, i2, ov1, oi1, ov2, oi2);
            }
            if ((lane & 3) == 0) {
                int row = wm * 64 + mf * 16 + (lane >> 2) + half * 8;
                s_red[row * 4 + wn] = make_int4(v1, i1, v2, i2);
            }
        }
    }
    __syncthreads();

    if (tid < BM) {
        int4 t = s_red[tid * 4 + 0];
        int v1 = t.x, i1 = t.y, v2 = t.z, i2 = t.w;
#pragma unroll
        for (int w = 1; w < 4; ++w) {
            int4 u = s_red[tid * 4 + w];
            top2i_merge(v1, i1, v2, i2, u.x, u.y, u.z, u.w);
        }
        const float cs = g_ascale[m0 + tid] *
                         (__uint_as_float(g_wamax_bits) * (1.f / 127.f));
        size_t o = (size_t)(m0 + tid) * NTILES + blockIdx.y;
        g_c1v[o] = (float)v1 * cs; g_c1i[o] = i1;
        g_c2v[o] = (float)v2 * cs; g_c2i[o] = i2;
    }
}

// ---------------------------------------------------------------------------
// Kernel 2: candidate merge + exact fp32 rescore -> g_maxidx (1 warp/row)
// ---------------------------------------------------------------------------
#define MAXCAND 96
#define NC (2*NTILES)
__global__ void finalize_kernel(const float* __restrict__ A, const float* __restrict__ W)
{
    const int wip = threadIdx.x >> 5;
    const int lane = threadIdx.x & 31;
    const int row = blockIdx.x * 8 + wip;
    __shared__ int s_cnt[8];
    __shared__ int s_idx[8][MAXCAND];

    float mx = -INFINITY;
    for (int i = lane; i < NC; i += 32) {
        float v = (i < NTILES) ? g_c1v[(size_t)row * NTILES + i]
                               : g_c2v[(size_t)row * NTILES + (i - NTILES)];
        mx = fmaxf(mx, v);
    }
#pragma unroll
    for (int off = 16; off > 0; off >>= 1)
        mx = fmaxf(mx, __shfl_xor_sync(0xffffffffu, mx, off));

    const float thr = mx - 0.10f;          // ~14 sigma of int8 quant noise
    if (lane == 0) s_cnt[wip] = 0;
    __syncwarp();
    for (int i = lane; i < NC; i += 32) {
        float v; int id;
        if (i < NTILES) { v = g_c1v[(size_t)row * NTILES + i]; id = g_c1i[(size_t)row * NTILES + i]; }
        else { v = g_c2v[(size_t)row * NTILES + (i - NTILES)]; id = g_c2i[(size_t)row * NTILES + (i - NTILES)]; }
        if (v >= thr) {
            int p = atomicAdd(&s_cnt[wip], 1);
            if (p < MAXCAND) s_idx[wip][p] = id;
        }
    }
    __syncwarp();
    int cnt = min(s_cnt[wip], MAXCAND);
    if (lane == 0) {
        for (int a = 1; a < cnt; ++a) {
            int key = s_idx[wip][a]; int b = a - 1;
            while (b >= 0 && s_idx[wip][b] > key) { s_idx[wip][b + 1] = s_idx[wip][b]; --b; }
            s_idx[wip][b + 1] = key;
        }
    }
    __syncwarp();

    const float* arow = A + (size_t)row * Dd;
    float bestv = -INFINITY; int besti = 0;
    for (int c = 0; c < cnt; ++c) {
        const float* wrow = W + (size_t)s_idx[wip][c] * Dd;
        float s = 0.f;
#pragma unroll
        for (int k = 0; k < Dd / 32; ++k)
            s = fmaf(arow[lane + k * 32], wrow[lane + k * 32], s);
#pragma unroll
        for (int off = 16; off > 0; off >>= 1)
            s += __shfl_xor_sync(0xffffffffu, s, off);
        if (s > bestv) { bestv = s; besti = s_idx[wip][c]; }
    }
    if (lane == 0) g_maxidx[row] = besti;
}

// ---------------------------------------------------------------------------
// Kernel 3: scores[r] = sqrt(D) * dot(outputs[n,t,:], W[maxidx[r],:]) (fp32)
// ---------------------------------------------------------------------------
__global__ void scores_kernel(const float* __restrict__ outputs,
                              const float* __restrict__ W)
{
    int gthread = blockIdx.x * blockDim.x + threadIdx.x;
    int warp = gthread >> 5;
    int lane = threadIdx.x & 31;
    if (warp >= Mm) return;

    int n = warp >> 10;
    int t = (warp & 1023) >> 2;

    const float* orow = outputs + ((size_t)(n * Tt + t)) * Dd;
    const float* wrow = W + (size_t)g_maxidx[warp] * Dd;

    float s = 0.f;
#pragma unroll
    for (int k = 0; k < Dd / 32; ++k)
        s = fmaf(orow[lane + k * 32], wrow[lane + k * 32], s);
#pragma unroll
    for (int off = 16; off > 0; off >>= 1)
        s += __shfl_xor_sync(0xffffffffu, s, off);

    if (lane == 0)
        g_scores[warp] = s * 22.62741699796952f;   // float32(sqrt(512))
}

// ---------------------------------------------------------------------------
// JAX threefry2x32 (bit-exact), partitionable random_bits construction.
// ---------------------------------------------------------------------------
__device__ __forceinline__ uint32_t rotl32(uint32_t x, int d)
{ return (x << d) | (x >> (32 - d)); }

__device__ __forceinline__ void threefry2x32(uint32_t k0, uint32_t k1,
                                             uint32_t x0, uint32_t x1,
                                             uint32_t& o0, uint32_t& o1)
{
    uint32_t k2 = k0 ^ k1 ^ 0x1BD11BDAu;
    x0 += k0; x1 += k1;
    x0 += x1; x1 = rotl32(x1, 13); x1 ^= x0;
    x0 += x1; x1 = rotl32(x1, 15); x1 ^= x0;
    x0 += x1; x1 = rotl32(x1, 26); x1 ^= x0;
    x0 += x1; x1 = rotl32(x1,  6); x1 ^= x0;
    x0 += k1; x1 += k2 + 1u;
    x0 += x1; x1 = rotl32(x1, 17); x1 ^= x0;
    x0 += x1; x1 = rotl32(x1, 29); x1 ^= x0;
    x0 += x1; x1 = rotl32(x1, 16); x1 ^= x0;
    x0 += x1; x1 = rotl32(x1, 24); x1 ^= x0;
    x0 += k2; x1 += k0 + 2u;
    x0 += x1; x1 = rotl32(x1, 13); x1 ^= x0;
    x0 += x1; x1 = rotl32(x1, 15); x1 ^= x0;
    x0 += x1; x1 = rotl32(x1, 26); x1 ^= x0;
    x0 += x1; x1 = rotl32(x1,  6); x1 ^= x0;
    x0 += k0; x1 += k1 + 3u;
    x0 += x1; x1 = rotl32(x1, 17); x1 ^= x0;
    x0 += x1; x1 = rotl32(x1, 29); x1 ^= x0;
    x0 += x1; x1 = rotl32(x1, 16); x1 ^= x0;
    x0 += x1; x1 = rotl32(x1, 24); x1 ^= x0;
    x0 += k1; x1 += k2 + 4u;
    x0 += x1; x1 = rotl32(x1, 13); x1 ^= x0;
    x0 += x1; x1 = rotl32(x1, 15); x1 ^= x0;
    x0 += x1; x1 = rotl32(x1, 26); x1 ^= x0;
    x0 += x1; x1 = rotl32(x1,  6); x1 ^= x0;
    x0 += k2; x1 += k0 + 5u;
    o0 = x0; o1 = x1;
}

// ---------------------------------------------------------------------------
// Kernel 4: logit thresholds in parallel, then 8-lane serial scan.
// ---------------------------------------------------------------------------
__global__ void scan_kernel(float* __restrict__ out)
{
    __shared__ float s_sc[Mm];
    __shared__ float s_thr[Tt][8];

    int tid = threadIdx.x;

    for (int i = tid; i < Mm; i += 256) { out[i] = 0.f; s_sc[i] = g_scores[i]; }

    {
        int t = tid;
        uint32_t kt0, kt1;
        threefry2x32(0u, 42u, 0u, (uint32_t)t, kt0, kt1);
#pragma unroll
        for (int n = 0; n < 8; ++n) {
            uint32_t o0, o1;
            threefry2x32(kt0, kt1, 0u, (uint32_t)n, o0, o1);
            uint32_t bits = (o0 ^ o1) >> 9;
            float u = __uint_as_float(bits | 0x3f800000u) - 1.0f;
            double du = (double)u;
            s_thr[t][n] = (float)(10.0 * log(du / (1.0 - du)));
        }
    }
    __syncthreads();

    if (tid < 8) {
        int n = tid;
        int x = 0, y = 0;
        const float* scn = s_sc + n * 1024;
        float* outn = out + n * 1024;
        for (int t = 0; t < Tt; ++t) {
            int idx0 = x * Bb + y;
            outn[idx0] = 1.0f;
            float z = scn[idx0] - scn[t * 4];
            int accept = (z > s_thr[t][n]) ? 1 : 0;
            if (y + accept >= Bb) accept = 0;
            y = (y + accept) * accept;
            x = accept ? x : (t + 1);
        }
    }
}

// ---------------------------------------------------------------------------
extern "C" void kernel_launch(void* const* d_in, const int* in_sizes, int n_in,
                              void* d_out, int out_size)
{
    (void)in_sizes; (void)n_in; (void)out_size;
    const float* outputs       = (const float*)d_in[0];   // [N,T,D]
    const float* block_outputs = (const float*)d_in[1];   // [N,T,B,D]
    const float* W             = (const float*)d_in[2];   // [V,D]
    float* out = (float*)d_out;                            // [N,T,B]

    quantA_kernel<<<Mm / 8, 256>>>(block_outputs);
    wmax_kernel<<<256, 256>>>(W);
    quantW_kernel<<<(Vv * Dd / 16) / 256, 256>>>(W);
    argmax_gemm_kernel<<<dim3(Mm / BM, NTILES), 256>>>();
    finalize_kernel<<<Mm / 8, 256>>>(block_outputs, W);
    scores_kernel<<<(Mm * 32) / 256, 256>>>(outputs, W);
    scan_kernel<<<1, 256>>>(out);
}

// round 5
// speedup vs baseline: 1.3879x; 1.3879x over previous
#include <cuda_runtime.h>
#include <cuda_bf16.h>
#include <stdint.h>
#include <math.h>

// Problem constants
#define Nn 8
#define Tt 256
#define Bb 4
#define Dd 512
#define Vv 32000
#define Mm (Nn*Tt*Bb)          // 8192 rows

// GEMM tiling (bf16 HMMA)
#define BM 128
#define BN 256
#define BK 32                  // K elems per stage (64 bytes)
#define NUM_K (Dd/BK)          // 16
#define NTILES (Vv/BN)         // 125
#define SSTRIDE_B 80           // 64B data + 16B pad per row (conflict-free)

// smem: [A buf 128*80=10240][B buf 256*80=20480] x2 = 61440 bytes
#define SMA(b) ((b)*30720)
#define SMB(b) ((b)*30720 + 10240)
#define SMEM_GEMM 61440

// ---------------------------------------------------------------------------
// Device scratch (no allocations allowed)
// ---------------------------------------------------------------------------
__device__ __align__(16) __nv_bfloat16 g_Abf[Mm*Dd];   // 8 MB
__device__ __align__(16) __nv_bfloat16 g_Wbf[Vv*Dd];   // 32 MB
__device__ float g_c1v[Mm*NTILES];
__device__ int   g_c1i[Mm*NTILES];
__device__ float g_c2v[Mm*NTILES];
__device__ int   g_c2i[Mm*NTILES];
__device__ float g_scores[Mm];

// ---------------------------------------------------------------------------
__device__ __forceinline__ uint32_t smem_u32(const void* p) {
    uint32_t a;
    asm("{ .reg .u64 t; cvta.to.shared.u64 t, %1; cvt.u32.u64 %0, t; }" : "=r"(a) : "l"(p));
    return a;
}
__device__ __forceinline__ void cp_async16(uint32_t s, const void* g) {
    asm volatile("cp.async.cg.shared.global [%0], [%1], 16;" :: "r"(s), "l"(g) : "memory");
}
__device__ __forceinline__ void cp_commit() {
    asm volatile("cp.async.commit_group;" ::: "memory");
}
template <int N>
__device__ __forceinline__ void cp_wait() {
    asm volatile("cp.async.wait_group %0;" :: "n"(N) : "memory");
}
__device__ __forceinline__ void ldsm_x4(uint32_t& a0, uint32_t& a1, uint32_t& a2,
                                        uint32_t& a3, uint32_t addr) {
    asm volatile("ldmatrix.sync.aligned.m8n8.x4.shared.b16 {%0,%1,%2,%3}, [%4];"
                 : "=r"(a0), "=r"(a1), "=r"(a2), "=r"(a3) : "r"(addr));
}
__device__ __forceinline__ void ldsm_x2(uint32_t& b0, uint32_t& b1, uint32_t addr) {
    asm volatile("ldmatrix.sync.aligned.m8n8.x2.shared.b16 {%0,%1}, [%2];"
                 : "=r"(b0), "=r"(b1) : "r"(addr));
}
__device__ __forceinline__ void mma_bf16(float* c, uint32_t a0, uint32_t a1,
                                         uint32_t a2, uint32_t a3,
                                         uint32_t b0, uint32_t b1) {
    asm volatile("mma.sync.aligned.m16n8k16.row.col.f32.bf16.bf16.f32 "
                 "{%0,%1,%2,%3}, {%4,%5,%6,%7}, {%8,%9}, {%0,%1,%2,%3};"
                 : "+f"(c[0]), "+f"(c[1]), "+f"(c[2]), "+f"(c[3])
                 : "r"(a0), "r"(a1), "r"(a2), "r"(a3), "r"(b0), "r"(b1));
}

__device__ __forceinline__ void top2_insert(float& v1, int& i1, float& v2, int& i2,
                                            float v, int idx) {
    if (v > v1) { v2 = v1; i2 = i1; v1 = v; i1 = idx; }
    else if (v > v2) { v2 = v; i2 = idx; }
}
__device__ __forceinline__ void top2_merge(float& v1, int& i1, float& v2, int& i2,
                                           float ov1, int oi1, float ov2, int oi2) {
    if (ov1 > v1) {
        if (v1 > ov2) { v2 = v1; i2 = i1; } else { v2 = ov2; i2 = oi2; }
        v1 = ov1; i1 = oi1;
    } else {
        if (ov1 > v2) { v2 = ov1; i2 = oi1; }
    }
}

// ---------------------------------------------------------------------------
// Kernel 0: fp32 -> bf16 conversion for A (block_outputs) and W
// ---------------------------------------------------------------------------
#define A4 (Mm*Dd/4)
#define W4 (Vv*Dd/4)
__global__ void convert_kernel(const float* __restrict__ A, const float* __restrict__ W)
{
    int i = blockIdx.x * blockDim.x + threadIdx.x;
    if (i < A4) {
        float4 v = ((const float4*)A)[i];
        __nv_bfloat162 p0 = __floats2bfloat162_rn(v.x, v.y);
        __nv_bfloat162 p1 = __floats2bfloat162_rn(v.z, v.w);
        *(uint2*)(g_Abf + (size_t)i * 4) = make_uint2(*(uint32_t*)&p0, *(uint32_t*)&p1);
    } else if (i < A4 + W4) {
        int j = i - A4;
        float4 v = ((const float4*)W)[j];
        __nv_bfloat162 p0 = __floats2bfloat162_rn(v.x, v.y);
        __nv_bfloat162 p1 = __floats2bfloat162_rn(v.z, v.w);
        *(uint2*)(g_Wbf + (size_t)j * 4) = make_uint2(*(uint32_t*)&p0, *(uint32_t*)&p1);
    }
}

// ---------------------------------------------------------------------------
// Kernel 1: bf16 HMMA GEMM 128x256 CTA, 64x64 warp tiles, cp.async pipeline.
// Epilogue: per-row top-2 over the 256-column V tile.
// Grid (Mm/BM=64, NTILES=125), 256 threads = 8 warps (2 M x 4 N).
// ---------------------------------------------------------------------------
__device__ __forceinline__ void stage_load(char* smem, int buf, int m0, int v0,
                                           int kt, int tid)
{
    const int kb = kt * (BK * 2);   // byte offset along K
#pragma unroll
    for (int i = 0; i < 6; ++i) {
        int slot = tid + i * 256;   // 0..1535
        if (slot < 512) {           // A: 128 rows x 4 chunks of 16B
            int r = slot >> 2, c = (slot & 3) * 16;
            cp_async16(smem_u32(smem + SMA(buf) + r * SSTRIDE_B + c),
                       (const char*)g_Abf + (size_t)(m0 + r) * (Dd * 2) + kb + c);
        } else {                    // B: 256 rows x 4 chunks of 16B
            int s = slot - 512;
            int r = s >> 2, c = (s & 3) * 16;
            cp_async16(smem_u32(smem + SMB(buf) + r * SSTRIDE_B + c),
                       (const char*)g_Wbf + (size_t)(v0 + r) * (Dd * 2) + kb + c);
        }
    }
    cp_commit();
}

__global__ void __launch_bounds__(256, 1)
argmax_gemm_kernel()
{
    extern __shared__ __align__(16) char smem[];

    const int tid = threadIdx.x;
    const int lane = tid & 31, wid = tid >> 5;
    const int wm = wid >> 2, wn = wid & 3;       // 2 x 4 warp grid
    const int m0 = blockIdx.x * BM;
    const int v0 = blockIdx.y * BN;

    const uint32_t sbase = smem_u32(smem);

    // ldmatrix addressing
    const int aRow = lane & 15;                  // A: rows within 16-row frag
    const int aK16 = (lane >> 4) * 16;           // A: 16B half-select
    const int l2 = lane & 15;
    const int bRow = l2 & 7;                     // B: col-row within 8
    const int bK16 = ((l2 >> 3) & 1) * 16;

    float acc[4][8][4];
#pragma unroll
    for (int a = 0; a < 4; ++a)
#pragma unroll
        for (int b = 0; b < 8; ++b)
#pragma unroll
            for (int c = 0; c < 4; ++c) acc[a][b][c] = 0.f;

    stage_load(smem, 0, m0, v0, 0, tid);

    for (int kt = 0; kt < NUM_K; ++kt) {
        const int buf = kt & 1;
        if (kt + 1 < NUM_K) {
            stage_load(smem, buf ^ 1, m0, v0, kt + 1, tid);
            cp_wait<1>();
        } else {
            cp_wait<0>();
        }
        __syncthreads();

        const uint32_t sa = sbase + SMA(buf);
        const uint32_t sb = sbase + SMB(buf);
#pragma unroll
        for (int s = 0; s < 2; ++s) {            // two k16 steps per stage
            uint32_t bf[8][2];
#pragma unroll
            for (int nf = 0; nf < 8; ++nf) {
                uint32_t addr = sb +
                    (uint32_t)((wn * 64 + nf * 8 + bRow) * SSTRIDE_B + s * 32 + bK16);
                ldsm_x2(bf[nf][0], bf[nf][1], addr);
            }
#pragma unroll
            for (int mf = 0; mf < 4; ++mf) {
                uint32_t a0, a1, a2, a3;
                uint32_t addr = sa +
                    (uint32_t)((wm * 64 + mf * 16 + aRow) * SSTRIDE_B + s * 32 + aK16);
                ldsm_x4(a0, a1, a2, a3, addr);
#pragma unroll
                for (int nf = 0; nf < 8; ++nf)
                    mma_bf16(acc[mf][nf], a0, a1, a2, a3, bf[nf][0], bf[nf][1]);
            }
        }
        __syncthreads();
    }

    // Epilogue: per-row top-2 over this CTA's 256 V-columns
    float4* s_red = (float4*)smem;               // [128 rows][4 N-warps], 8 KB
    const int colBase = v0 + wn * 64 + (lane & 3) * 2;

#pragma unroll
    for (int mf = 0; mf < 4; ++mf) {
#pragma unroll
        for (int half = 0; half < 2; ++half) {
            float v1 = -INFINITY, v2 = -INFINITY;
            int i1 = 0, i2 = 0;
#pragma unroll
            for (int nf = 0; nf < 8; ++nf) {
#pragma unroll
                for (int c = 0; c < 2; ++c)
                    top2_insert(v1, i1, v2, i2, acc[mf][nf][half * 2 + c],
                                colBase + nf * 8 + c);
            }
#pragma unroll
            for (int off = 2; off >= 1; off >>= 1) {
                float ov1 = __shfl_down_sync(0xffffffffu, v1, off, 4);
                int   oi1 = __shfl_down_sync(0xffffffffu, i1, off, 4);
                float ov2 = __shfl_down_sync(0xffffffffu, v2, off, 4);
                int   oi2 = __shfl_down_sync(0xffffffffu, i2, off, 4);
                top2_merge(v1, i1, v2, i2, ov1, oi1, ov2, oi2);
            }
            if ((lane & 3) == 0) {
                int row = wm * 64 + mf * 16 + (lane >> 2) + half * 8;
                s_red[row * 4 + wn] =
                    make_float4(v1, __int_as_float(i1), v2, __int_as_float(i2));
            }
        }
    }
    __syncthreads();

    if (tid < BM) {
        float4 t = s_red[tid * 4 + 0];
        float v1 = t.x, v2 = t.z;
        int i1 = __float_as_int(t.y), i2 = __float_as_int(t.w);
#pragma unroll
        for (int w = 1; w < 4; ++w) {
            float4 u = s_red[tid * 4 + w];
            top2_merge(v1, i1, v2, i2, u.x, __float_as_int(u.y),
                       u.z, __float_as_int(u.w));
        }
        size_t o = (size_t)(m0 + tid) * NTILES + blockIdx.y;
        g_c1v[o] = v1; g_c1i[o] = i1;
        g_c2v[o] = v2; g_c2i[o] = i2;
    }
}

// ---------------------------------------------------------------------------
// Kernel 2: candidate merge + exact fp32 rescore -> argmax; then the final
// score = sqrt(D) * dot(outputs[n,t,:], W[argmax,:]).  One warp per row.
// ---------------------------------------------------------------------------
#define MAXCAND 96
#define NC (2*NTILES)
__global__ void finalize_kernel(const float* __restrict__ A,
                                const float* __restrict__ W,
                                const float* __restrict__ outputs)
{
    const int wip = threadIdx.x >> 5;
    const int lane = threadIdx.x & 31;
    const int row = blockIdx.x * 8 + wip;
    __shared__ int s_cnt[8];
    __shared__ int s_idx[8][MAXCAND];

    float mx = -INFINITY;
    for (int i = lane; i < NC; i += 32) {
        float v = (i < NTILES) ? g_c1v[(size_t)row * NTILES + i]
                               : g_c2v[(size_t)row * NTILES + (i - NTILES)];
        mx = fmaxf(mx, v);
    }
#pragma unroll
    for (int off = 16; off > 0; off >>= 1)
        mx = fmaxf(mx, __shfl_xor_sync(0xffffffffu, mx, off));

    const float thr = mx - 0.04f;      // ~16 sigma of bf16 logit noise
    if (lane == 0) s_cnt[wip] = 0;
    __syncwarp();
    for (int i = lane; i < NC; i += 32) {
        float v; int id;
        if (i < NTILES) { v = g_c1v[(size_t)row * NTILES + i]; id = g_c1i[(size_t)row * NTILES + i]; }
        else { v = g_c2v[(size_t)row * NTILES + (i - NTILES)]; id = g_c2i[(size_t)row * NTILES + (i - NTILES)]; }
        if (v >= thr) {
            int p = atomicAdd(&s_cnt[wip], 1);
            if (p < MAXCAND) s_idx[wip][p] = id;
        }
    }
    __syncwarp();
    int cnt = min(s_cnt[wip], MAXCAND);
    if (lane == 0) {   // ascending index order -> deterministic first-max tie rule
        for (int a = 1; a < cnt; ++a) {
            int key = s_idx[wip][a]; int b = a - 1;
            while (b >= 0 && s_idx[wip][b] > key) { s_idx[wip][b + 1] = s_idx[wip][b]; --b; }
            s_idx[wip][b + 1] = key;
        }
    }
    __syncwarp();

    const float* arow = A + (size_t)row * Dd;
    float bestv = -INFINITY; int besti = 0;
    for (int c = 0; c < cnt; ++c) {
        const float* wrow = W + (size_t)s_idx[wip][c] * Dd;
        float s = 0.f;
#pragma unroll
        for (int k = 0; k < Dd / 32; ++k)
            s = fmaf(arow[lane + k * 32], wrow[lane + k * 32], s);
#pragma unroll
        for (int off = 16; off > 0; off >>= 1)
            s += __shfl_xor_sync(0xffffffffu, s, off);
        if (s > bestv) { bestv = s; besti = s_idx[wip][c]; }
    }

    // Final score with the chosen embedding row (exact fp32)
    {
        int n = row >> 10;
        int t = (row & 1023) >> 2;
        const float* orow = outputs + ((size_t)(n * Tt + t)) * Dd;
        const float* wrow = W + (size_t)besti * Dd;
        float s = 0.f;
#pragma unroll
        for (int k = 0; k < Dd / 32; ++k)
            s = fmaf(orow[lane + k * 32], wrow[lane + k * 32], s);
#pragma unroll
        for (int off = 16; off > 0; off >>= 1)
            s += __shfl_xor_sync(0xffffffffu, s, off);
        if (lane == 0)
            g_scores[row] = s * 22.62741699796952f;   // float32(sqrt(512))
    }
}

// ---------------------------------------------------------------------------
// JAX threefry2x32 (bit-exact), partitionable random_bits construction.
// ---------------------------------------------------------------------------
__device__ __forceinline__ uint32_t rotl32(uint32_t x, int d)
{ return (x << d) | (x >> (32 - d)); }

__device__ __forceinline__ void threefry2x32(uint32_t k0, uint32_t k1,
                                             uint32_t x0, uint32_t x1,
                                             uint32_t& o0, uint32_t& o1)
{
    uint32_t k2 = k0 ^ k1 ^ 0x1BD11BDAu;
    x0 += k0; x1 += k1;
    x0 += x1; x1 = rotl32(x1, 13); x1 ^= x0;
    x0 += x1; x1 = rotl32(x1, 15); x1 ^= x0;
    x0 += x1; x1 = rotl32(x1, 26); x1 ^= x0;
    x0 += x1; x1 = rotl32(x1,  6); x1 ^= x0;
    x0 += k1; x1 += k2 + 1u;
    x0 += x1; x1 = rotl32(x1, 17); x1 ^= x0;
    x0 += x1; x1 = rotl32(x1, 29); x1 ^= x0;
    x0 += x1; x1 = rotl32(x1, 16); x1 ^= x0;
    x0 += x1; x1 = rotl32(x1, 24); x1 ^= x0;
    x0 += k2; x1 += k0 + 2u;
    x0 += x1; x1 = rotl32(x1, 13); x1 ^= x0;
    x0 += x1; x1 = rotl32(x1, 15); x1 ^= x0;
    x0 += x1; x1 = rotl32(x1, 26); x1 ^= x0;
    x0 += x1; x1 = rotl32(x1,  6); x1 ^= x0;
    x0 += k0; x1 += k1 + 3u;
    x0 += x1; x1 = rotl32(x1, 17); x1 ^= x0;
    x0 += x1; x1 = rotl32(x1, 29); x1 ^= x0;
    x0 += x1; x1 = rotl32(x1, 16); x1 ^= x0;
    x0 += x1; x1 = rotl32(x1, 24); x1 ^= x0;
    x0 += k1; x1 += k2 + 4u;
    x0 += x1; x1 = rotl32(x1, 13); x1 ^= x0;
    x0 += x1; x1 = rotl32(x1, 15); x1 ^= x0;
    x0 += x1; x1 = rotl32(x1, 26); x1 ^= x0;
    x0 += x1; x1 = rotl32(x1,  6); x1 ^= x0;
    x0 += k2; x1 += k0 + 5u;
    o0 = x0; o1 = x1;
}

// ---------------------------------------------------------------------------
// Kernel 3: logit thresholds in parallel, then 8-lane serial scan.
// accept  <=>  u < sigmoid(z/10)  <=>  z > 10*logit(u)
// ---------------------------------------------------------------------------
__global__ void scan_kernel(float* __restrict__ out)
{
    __shared__ float s_sc[Mm];
    __shared__ float s_thr[Tt][8];

    int tid = threadIdx.x;

    for (int i = tid; i < Mm; i += 256) { out[i] = 0.f; s_sc[i] = g_scores[i]; }

    {
        int t = tid;
        uint32_t kt0, kt1;
        threefry2x32(0u, 42u, 0u, (uint32_t)t, kt0, kt1);
#pragma unroll
        for (int n = 0; n < 8; ++n) {
            uint32_t o0, o1;
            threefry2x32(kt0, kt1, 0u, (uint32_t)n, o0, o1);
            uint32_t bits = (o0 ^ o1) >> 9;
            float u = __uint_as_float(bits | 0x3f800000u) - 1.0f;
            double du = (double)u;
            s_thr[t][n] = (float)(10.0 * log(du / (1.0 - du)));
        }
    }
    __syncthreads();

    if (tid < 8) {
        int n = tid;
        int x = 0, y = 0;
        const float* scn = s_sc + n * 1024;
        float* outn = out + n * 1024;
        for (int t = 0; t < Tt; ++t) {
            int idx0 = x * Bb + y;
            outn[idx0] = 1.0f;
            float z = scn[idx0] - scn[t * 4];
            int accept = (z > s_thr[t][n]) ? 1 : 0;
            if (y + accept >= Bb) accept = 0;
            y = (y + accept) * accept;
            x = accept ? x : (t + 1);
        }
    }
}

// ---------------------------------------------------------------------------
extern "C" void kernel_launch(void* const* d_in, const int* in_sizes, int n_in,
                              void* d_out, int out_size)
{
    (void)in_sizes; (void)n_in; (void)out_size;
    const float* outputs       = (const float*)d_in[0];   // [N,T,D]
    const float* block_outputs = (const float*)d_in[1];   // [N,T,B,D]
    const float* W             = (const float*)d_in[2];   // [V,D]
    float* out = (float*)d_out;                            // [N,T,B]

    cudaFuncSetAttribute(argmax_gemm_kernel,
                         cudaFuncAttributeMaxDynamicSharedMemorySize, SMEM_GEMM);

    convert_kernel<<<(A4 + W4 + 255) / 256, 256>>>(block_outputs, W);
    argmax_gemm_kernel<<<dim3(Mm / BM, NTILES), 256, SMEM_GEMM>>>();
    finalize_kernel<<<Mm / 8, 256>>>(block_outputs, W, outputs);
    scan_kernel<<<1, 256>>>(out);
}

// round 6
// speedup vs baseline: 1.6565x; 1.1936x over previous
#include <cuda_runtime.h>
#include <cuda_fp16.h>
#include <stdint.h>
#include <math.h>

// Problem constants
#define Nn 8
#define Tt 256
#define Bb 4
#define Dd 512
#define Vv 32000
#define Mm (Nn*Tt*Bb)          // 8192 rows

// GEMM tiling (fp16 HMMA, fp16 accumulate)
#define BM 128
#define BN 128
#define BK 32
#define NUM_K (Dd/BK)          // 16
#define NTILES (Vv/BN)         // 250
#define NG (Vv/32)             // 1000 column-groups of 32 per row
#define SA_STRIDE 40           // 32 + 8 pad halfs -> 80B rows (conflict-free)

// ---------------------------------------------------------------------------
// Device scratch (no allocations allowed)
// ---------------------------------------------------------------------------
__device__ __align__(16) __half g_Ah[Mm*Dd];      // 8 MB
__device__ __align__(16) __half g_Wh[Vv*Dd];      // 32 MB
__device__ __align__(16) float4 g_cand[(size_t)Mm*NG];  // (v1,i1,v2,i2) 128 MB
__device__ float g_scores[Mm];

// ---------------------------------------------------------------------------
__device__ __forceinline__ uint32_t smem_u32(const void* p) {
    uint32_t a;
    asm("{ .reg .u64 t; cvta.to.shared.u64 t, %1; cvt.u32.u64 %0, t; }" : "=r"(a) : "l"(p));
    return a;
}
__device__ __forceinline__ void ldsm_x4(uint32_t& a0, uint32_t& a1, uint32_t& a2,
                                        uint32_t& a3, uint32_t addr) {
    asm volatile("ldmatrix.sync.aligned.m8n8.x4.shared.b16 {%0,%1,%2,%3}, [%4];"
                 : "=r"(a0), "=r"(a1), "=r"(a2), "=r"(a3) : "r"(addr));
}
__device__ __forceinline__ void ldsm_x2(uint32_t& b0, uint32_t& b1, uint32_t addr) {
    asm volatile("ldmatrix.sync.aligned.m8n8.x2.shared.b16 {%0,%1}, [%2];"
                 : "=r"(b0), "=r"(b1) : "r"(addr));
}
// fp16 inputs, fp16 accumulators (C/D are 2x f16x2 regs)
__device__ __forceinline__ void mma_f16acc(uint32_t* c, uint32_t a0, uint32_t a1,
                                           uint32_t a2, uint32_t a3,
                                           uint32_t b0, uint32_t b1) {
    asm volatile("mma.sync.aligned.m16n8k16.row.col.f16.f16.f16.f16 "
                 "{%0,%1}, {%2,%3,%4,%5}, {%6,%7}, {%0,%1};"
                 : "+r"(c[0]), "+r"(c[1])
                 : "r"(a0), "r"(a1), "r"(a2), "r"(a3), "r"(b0), "r"(b1));
}

__device__ __forceinline__ void top2_insert(float& v1, int& i1, float& v2, int& i2,
                                            float v, int idx) {
    if (v > v1) { v2 = v1; i2 = i1; v1 = v; i1 = idx; }
    else if (v > v2) { v2 = v; i2 = idx; }
}
__device__ __forceinline__ void top2_merge(float& v1, int& i1, float& v2, int& i2,
                                           float ov1, int oi1, float ov2, int oi2) {
    if (ov1 > v1) {
        if (v1 > ov2) { v2 = v1; i2 = i1; } else { v2 = ov2; i2 = oi2; }
        v1 = ov1; i1 = oi1;
    } else {
        if (ov1 > v2) { v2 = ov1; i2 = oi1; }
    }
}

// ---------------------------------------------------------------------------
// Kernel 0: fp32 -> fp16 conversion for A (block_outputs) and W
// ---------------------------------------------------------------------------
#define A4 (Mm*Dd/4)
#define W4 (Vv*Dd/4)
__global__ void convert_kernel(const float* __restrict__ A, const float* __restrict__ W)
{
    int i = blockIdx.x * blockDim.x + threadIdx.x;
    if (i < A4) {
        float4 v = ((const float4*)A)[i];
        __half2 p0 = __floats2half2_rn(v.x, v.y);
        __half2 p1 = __floats2half2_rn(v.z, v.w);
        *(uint2*)(g_Ah + (size_t)i * 4) = make_uint2(*(uint32_t*)&p0, *(uint32_t*)&p1);
    } else if (i < A4 + W4) {
        int j = i - A4;
        float4 v = ((const float4*)W)[j];
        __half2 p0 = __floats2half2_rn(v.x, v.y);
        __half2 p1 = __floats2half2_rn(v.z, v.w);
        *(uint2*)(g_Wh + (size_t)j * 4) = make_uint2(*(uint32_t*)&p0, *(uint32_t*)&p1);
    }
}

// ---------------------------------------------------------------------------
// Kernel 1: fp16 HMMA GEMM (fp16 acc) + per-warp top-2 over 32-col groups.
// Grid (Mm/BM=64, NTILES=250), 256 threads = 8 warps (2 M x 4 N), warp 64x32.
// Exact round-3 schedule (96% pipe) with halved accumulator registers.
// ---------------------------------------------------------------------------
__global__ void __launch_bounds__(256, 2)
argmax_gemm_kernel()
{
    __shared__ __align__(16) __half sA[2][BM * SA_STRIDE];
    __shared__ __align__(16) __half sB[2][BN * SA_STRIDE];

    const int tid = threadIdx.x;
    const int lane = tid & 31, wid = tid >> 5;
    const int wm = wid >> 2, wn = wid & 3;
    const int m0 = blockIdx.x * BM;
    const int v0 = blockIdx.y * BN;

    // Global load mapping: 512 uint4 slots per tile; thread does rows lr, lr+64
    const int lr = tid >> 2;
    const int lc = (tid & 3) * 8;
    const __half* gA = g_Ah + (size_t)(m0 + lr) * Dd + lc;
    const __half* gW = g_Wh + (size_t)(v0 + lr) * Dd + lc;
    const int smoff0 = lr * SA_STRIDE + lc;
    const int smoff1 = (lr + 64) * SA_STRIDE + lc;

    // ldmatrix addressing
    const int aRow = lane & 15;
    const int aKof = (lane >> 4) * 8;
    const int l2 = lane & 15;
    const int bRow = l2 & 7;
    const int bKof = ((l2 >> 3) & 1) * 8;

    uint32_t sa_base[2], sb_base[2];
    sa_base[0] = smem_u32(sA[0]); sa_base[1] = smem_u32(sA[1]);
    sb_base[0] = smem_u32(sB[0]); sb_base[1] = smem_u32(sB[1]);

    uint32_t acc[4][4][2];     // [mf][nf][half-pair], f16x2 each
#pragma unroll
    for (int a = 0; a < 4; ++a)
#pragma unroll
        for (int b = 0; b < 4; ++b) { acc[a][b][0] = 0u; acc[a][b][1] = 0u; }

    uint4 ra0, ra1, rb0, rb1;

    ra0 = *(const uint4*)(gA);
    ra1 = *(const uint4*)(gA + (size_t)64 * Dd);
    rb0 = *(const uint4*)(gW);
    rb1 = *(const uint4*)(gW + (size_t)64 * Dd);
    *(uint4*)(sA[0] + smoff0) = ra0; *(uint4*)(sA[0] + smoff1) = ra1;
    *(uint4*)(sB[0] + smoff0) = rb0; *(uint4*)(sB[0] + smoff1) = rb1;
    __syncthreads();

    for (int kt = 0; kt < NUM_K; ++kt) {
        const int buf = kt & 1;
        if (kt + 1 < NUM_K) {
            int g = (kt + 1) * BK;
            ra0 = *(const uint4*)(gA + g);
            ra1 = *(const uint4*)(gA + g + (size_t)64 * Dd);
            rb0 = *(const uint4*)(gW + g);
            rb1 = *(const uint4*)(gW + g + (size_t)64 * Dd);
        }

#pragma unroll
        for (int s = 0; s < 2; ++s) {
            uint32_t bf[4][2];
#pragma unroll
            for (int nf = 0; nf < 4; ++nf) {
                uint32_t addr = sb_base[buf] +
                    2u * (uint32_t)((wn * 32 + nf * 8 + bRow) * SA_STRIDE + s * 16 + bKof);
                ldsm_x2(bf[nf][0], bf[nf][1], addr);
            }
#pragma unroll
            for (int mf = 0; mf < 4; ++mf) {
                uint32_t a0, a1, a2, a3;
                uint32_t addr = sa_base[buf] +
                    2u * (uint32_t)((wm * 64 + mf * 16 + aRow) * SA_STRIDE + s * 16 + aKof);
                ldsm_x4(a0, a1, a2, a3, addr);
#pragma unroll
                for (int nf = 0; nf < 4; ++nf)
                    mma_f16acc(acc[mf][nf], a0, a1, a2, a3, bf[nf][0], bf[nf][1]);
            }
        }

        if (kt + 1 < NUM_K) {
            const int nb = buf ^ 1;
            *(uint4*)(sA[nb] + smoff0) = ra0; *(uint4*)(sA[nb] + smoff1) = ra1;
            *(uint4*)(sB[nb] + smoff0) = rb0; *(uint4*)(sB[nb] + smoff1) = rb1;
        }
        __syncthreads();
    }

    // Epilogue: per-warp top-2 over this warp's 32 V-columns (one group).
    // Group id = blockIdx.y*4 + wn. No cross-warp merge needed.
    const int colBase = v0 + wn * 32 + (lane & 3) * 2;
    const int group = blockIdx.y * 4 + wn;

#pragma unroll
    for (int mf = 0; mf < 4; ++mf) {
#pragma unroll
        for (int half = 0; half < 2; ++half) {
            float v1 = -INFINITY, v2 = -INFINITY;
            int i1 = 0, i2 = 0;
#pragma unroll
            for (int nf = 0; nf < 4; ++nf) {
                float2 p = __half22float2(*(__half2*)&acc[mf][nf][half]);
                top2_insert(v1, i1, v2, i2, p.x, colBase + nf * 8);
                top2_insert(v1, i1, v2, i2, p.y, colBase + nf * 8 + 1);
            }
#pragma unroll
            for (int off = 2; off >= 1; off >>= 1) {
                float ov1 = __shfl_down_sync(0xffffffffu, v1, off, 4);
                int   oi1 = __shfl_down_sync(0xffffffffu, i1, off, 4);
                float ov2 = __shfl_down_sync(0xffffffffu, v2, off, 4);
                int   oi2 = __shfl_down_sync(0xffffffffu, i2, off, 4);
                top2_merge(v1, i1, v2, i2, ov1, oi1, ov2, oi2);
            }
            if ((lane & 3) == 0) {
                int row = m0 + wm * 64 + mf * 16 + (lane >> 2) + half * 8;
                g_cand[(size_t)row * NG + group] =
                    make_float4(v1, __int_as_float(i1), v2, __int_as_float(i2));
            }
        }
    }
}

// ---------------------------------------------------------------------------
// Kernel 2: candidate merge + exact fp32 rescore -> argmax; then the final
// score = sqrt(D) * dot(outputs[n,t,:], W[argmax,:]).  One warp per row.
// ---------------------------------------------------------------------------
#define MAXCAND 128
__global__ void finalize_kernel(const float* __restrict__ A,
                                const float* __restrict__ W,
                                const float* __restrict__ outputs)
{
    const int wip = threadIdx.x >> 5;
    const int lane = threadIdx.x & 31;
    const int row = blockIdx.x * 8 + wip;
    __shared__ int s_cnt[8];
    __shared__ int s_idx[8][MAXCAND];

    const float4* cand = g_cand + (size_t)row * NG;

    float mx = -INFINITY;
    for (int i = lane; i < NG; i += 32)
        mx = fmaxf(mx, cand[i].x);
#pragma unroll
    for (int off = 16; off > 0; off >>= 1)
        mx = fmaxf(mx, __shfl_xor_sync(0xffffffffu, mx, off));

    const float thr = mx - 0.15f;   // >=15 sigma of fp16-acc noise
    if (lane == 0) s_cnt[wip] = 0;
    __syncwarp();
    for (int i = lane; i < NG; i += 32) {
        float4 c = cand[i];
        if (c.x >= thr) {
            int p = atomicAdd(&s_cnt[wip], 1);
            if (p < MAXCAND) s_idx[wip][p] = __float_as_int(c.y);
        }
        if (c.z >= thr) {
            int p = atomicAdd(&s_cnt[wip], 1);
            if (p < MAXCAND) s_idx[wip][p] = __float_as_int(c.w);
        }
    }
    __syncwarp();
    int cnt = min(s_cnt[wip], MAXCAND);
    if (lane == 0) {   // ascending index -> deterministic first-max tie rule
        for (int a = 1; a < cnt; ++a) {
            int key = s_idx[wip][a]; int b = a - 1;
            while (b >= 0 && s_idx[wip][b] > key) { s_idx[wip][b + 1] = s_idx[wip][b]; --b; }
            s_idx[wip][b + 1] = key;
        }
    }
    __syncwarp();

    const float* arow = A + (size_t)row * Dd;
    float bestv = -INFINITY; int besti = 0;
    for (int c = 0; c < cnt; ++c) {
        const float* wrow = W + (size_t)s_idx[wip][c] * Dd;
        float s = 0.f;
#pragma unroll
        for (int k = 0; k < Dd / 32; ++k)
            s = fmaf(arow[lane + k * 32], wrow[lane + k * 32], s);
#pragma unroll
        for (int off = 16; off > 0; off >>= 1)
            s += __shfl_xor_sync(0xffffffffu, s, off);
        if (s > bestv) { bestv = s; besti = s_idx[wip][c]; }
    }

    // Final score with the chosen embedding row (exact fp32)
    {
        int n = row >> 10;
        int t = (row & 1023) >> 2;
        const float* orow = outputs + ((size_t)(n * Tt + t)) * Dd;
        const float* wrow = W + (size_t)besti * Dd;
        float s = 0.f;
#pragma unroll
        for (int k = 0; k < Dd / 32; ++k)
            s = fmaf(orow[lane + k * 32], wrow[lane + k * 32], s);
#pragma unroll
        for (int off = 16; off > 0; off >>= 1)
            s += __shfl_xor_sync(0xffffffffu, s, off);
        if (lane == 0)
            g_scores[row] = s * 22.62741699796952f;   // float32(sqrt(512))
    }
}

// ---------------------------------------------------------------------------
// JAX threefry2x32 (bit-exact), partitionable random_bits construction.
// ---------------------------------------------------------------------------
__device__ __forceinline__ uint32_t rotl32(uint32_t x, int d)
{ return (x << d) | (x >> (32 - d)); }

__device__ __forceinline__ void threefry2x32(uint32_t k0, uint32_t k1,
                                             uint32_t x0, uint32_t x1,
                                             uint32_t& o0, uint32_t& o1)
{
    uint32_t k2 = k0 ^ k1 ^ 0x1BD11BDAu;
    x0 += k0; x1 += k1;
    x0 += x1; x1 = rotl32(x1, 13); x1 ^= x0;
    x0 += x1; x1 = rotl32(x1, 15); x1 ^= x0;
    x0 += x1; x1 = rotl32(x1, 26); x1 ^= x0;
    x0 += x1; x1 = rotl32(x1,  6); x1 ^= x0;
    x0 += k1; x1 += k2 + 1u;
    x0 += x1; x1 = rotl32(x1, 17); x1 ^= x0;
    x0 += x1; x1 = rotl32(x1, 29); x1 ^= x0;
    x0 += x1; x1 = rotl32(x1, 16); x1 ^= x0;
    x0 += x1; x1 = rotl32(x1, 24); x1 ^= x0;
    x0 += k2; x1 += k0 + 2u;
    x0 += x1; x1 = rotl32(x1, 13); x1 ^= x0;
    x0 += x1; x1 = rotl32(x1, 15); x1 ^= x0;
    x0 += x1; x1 = rotl32(x1, 26); x1 ^= x0;
    x0 += x1; x1 = rotl32(x1,  6); x1 ^= x0;
    x0 += k0; x1 += k1 + 3u;
    x0 += x1; x1 = rotl32(x1, 17); x1 ^= x0;
    x0 += x1; x1 = rotl32(x1, 29); x1 ^= x0;
    x0 += x1; x1 = rotl32(x1, 16); x1 ^= x0;
    x0 += x1; x1 = rotl32(x1, 24); x1 ^= x0;
    x0 += k1; x1 += k2 + 4u;
    x0 += x1; x1 = rotl32(x1, 13); x1 ^= x0;
    x0 += x1; x1 = rotl32(x1, 15); x1 ^= x0;
    x0 += x1; x1 = rotl32(x1, 26); x1 ^= x0;
    x0 += x1; x1 = rotl32(x1,  6); x1 ^= x0;
    x0 += k2; x1 += k0 + 5u;
    o0 = x0; o1 = x1;
}

// ---------------------------------------------------------------------------
// Kernel 3: logit thresholds in parallel, then 8-lane serial scan.
// accept  <=>  u < sigmoid(z/10)  <=>  z > 10*logit(u)
// ---------------------------------------------------------------------------
__global__ void scan_kernel(float* __restrict__ out)
{
    __shared__ float s_sc[Mm];
    __shared__ float s_thr[Tt][8];

    int tid = threadIdx.x;

    for (int i = tid; i < Mm; i += 256) { out[i] = 0.f; s_sc[i] = g_scores[i]; }

    {
        int t = tid;
        uint32_t kt0, kt1;
        threefry2x32(0u, 42u, 0u, (uint32_t)t, kt0, kt1);
#pragma unroll
        for (int n = 0; n < 8; ++n) {
            uint32_t o0, o1;
            threefry2x32(kt0, kt1, 0u, (uint32_t)n, o0, o1);
            uint32_t bits = (o0 ^ o1) >> 9;
            float u = __uint_as_float(bits | 0x3f800000u) - 1.0f;
            double du = (double)u;
            s_thr[t][n] = (float)(10.0 * log(du / (1.0 - du)));
        }
    }
    __syncthreads();

    if (tid < 8) {
        int n = tid;
        int x = 0, y = 0;
        const float* scn = s_sc + n * 1024;
        float* outn = out + n * 1024;
        for (int t = 0; t < Tt; ++t) {
            int idx0 = x * Bb + y;
            outn[idx0] = 1.0f;
            float z = scn[idx0] - scn[t * 4];
            int accept = (z > s_thr[t][n]) ? 1 : 0;
            if (y + accept >= Bb) accept = 0;
            y = (y + accept) * accept;
            x = accept ? x : (t + 1);
        }
    }
}

// ---------------------------------------------------------------------------
extern "C" void kernel_launch(void* const* d_in, const int* in_sizes, int n_in,
                              void* d_out, int out_size)
{
    (void)in_sizes; (void)n_in; (void)out_size;
    const float* outputs       = (const float*)d_in[0];   // [N,T,D]
    const float* block_outputs = (const float*)d_in[1];   // [N,T,B,D]
    const float* W             = (const float*)d_in[2];   // [V,D]
    float* out = (float*)d_out;                            // [N,T,B]

    convert_kernel<<<(A4 + W4 + 255) / 256, 256>>>(block_outputs, W);
    argmax_gemm_kernel<<<dim3(Mm / BM, NTILES), 256>>>();
    finalize_kernel<<<Mm / 8, 256>>>(block_outputs, W, outputs);
    scan_kernel<<<1, 256>>>(out);
}